// round 8
// baseline (speedup 1.0000x reference)
#include <cuda_runtime.h>

// Fixed problem shape
#define BB 256
#define TT 4096
#define CC 16
#define HH 20
#define GG 60
#define K  16
#define NC (TT / K)   // 256 chunks

typedef unsigned long long u64;

// gx0 scratch: [B, T, 60] fp32 = 251 MB (device global; no alloc allowed)
__device__ float g_gx0[(size_t)BB * TT * GG];

__device__ __forceinline__ u64 pack2(float a, float b) {
    u64 r; asm("mov.b64 %0,{%1,%2};" : "=l"(r) : "f"(a), "f"(b)); return r;
}
__device__ __forceinline__ void fma2(u64& d, u64 a, u64 b) {
    asm("fma.rn.f32x2 %0,%1,%2,%0;" : "+l"(d) : "l"(a), "l"(b));
}
__device__ __forceinline__ float hsum2(u64 v) {
    float x, y; asm("mov.b64 {%0,%1},%2;" : "=f"(x), "=f"(y) : "l"(v)); return x + y;
}
__device__ __forceinline__ float tanha(float x) {
    float y; asm("tanh.approx.f32 %0,%1;" : "=f"(y) : "f"(x)); return y;
}

// ---------------------------------------------------------------------------
// Kernel A: gx0[bt,g] = sc_g * (b_ih0[g] + sum_c x[bt,c] W_ih0[g,c]),
// sc_g = 0.5 for r,z gate rows (g < 40), 1.0 for n rows. Bulk parallel GEMM.
// ---------------------------------------------------------------------------
__global__ void gx0_kernel(const float* __restrict__ x,
                           const float* __restrict__ W,
                           const float* __restrict__ bias) {
    __shared__ float xs[4][CC];
    size_t bt = (size_t)blockIdx.x * 4 + threadIdx.y;
    if (threadIdx.x < CC)
        xs[threadIdx.y][threadIdx.x] = x[bt * CC + threadIdx.x];
    __syncthreads();
    int g = threadIdx.x;
    if (g < GG) {
        float acc = bias[g];
#pragma unroll
        for (int c = 0; c < CC; ++c)
            acc += xs[threadIdx.y][c] * W[g * CC + c];
        const float sc = (g < 2 * HH) ? 0.5f : 1.0f;
        g_gx0[bt * GG + g] = sc * acc;
    }
}

// ---------------------------------------------------------------------------
// Kernel B: fused recurrent pipeline. 2 batches per block, 8 warps.
// Warp map (SMSP = w%4; chain warps at HIGH wid on each SMSP):
//   w0=GX1rz(A) S0   w1=GX1n+DMA+head(A) S1   w2=GX1rz(B) S2   w3=GX1n..(B) S3
//   w4=L0(A)    S0   w5=L1(A)            S1   w6=L0(B)    S2   w7=L1(B)   S3
// Iteration c (one __syncthreads, 2-deep rings):
//   DMA (w1/w3): gx0 chunk c+1  global -> s_gx0
//   L0:          chunk c        s_gx0 -> s_h0          (pure 30-fma2 chain)
//   GX1rz/GX1n:  chunk c-1      s_h0 -> s_gx1          (gx1 = W_ih1.h0)
//   L1:          chunk c-2      s_gx1 -> s_h1          (pure chain)
//   head (w1/w3):chunk c-3      s_h1 -> out  (16 dots parallel across lanes)
// Chains exchange h through their own s_h ring rows (STS + syncwarp + LDS.64),
// which simultaneously hands h to the GX1/head consumers.
// r/z weights, biases and gx rows are pre-scaled by 0.5:
//   sigmoid(s) = fma(tanh.approx(prescaled_sum), 0.5, 0.5).
// ---------------------------------------------------------------------------
__global__ void __launch_bounds__(256, 1)
gru_main_kernel(const float* __restrict__ h0in,   // [B,2,H]
                const float* __restrict__ W_hh0, const float* __restrict__ b_hh0,
                const float* __restrict__ W_ih1, const float* __restrict__ b_ih1,
                const float* __restrict__ W_hh1, const float* __restrict__ b_hh1,
                const float* __restrict__ W_o,   const float* __restrict__ b_o,
                float* __restrict__ out)          // o[B*T] then h_n[B,2,H]
{
    __shared__ __align__(16) float s_gx0[2][2][K][GG];  // 15 KB
    __shared__ __align__(16) float s_gx1[2][2][K][GG];  // 15 KB
    __shared__ __align__(16) float s_h0 [2][2][K][HH];  // 5 KB
    __shared__ __align__(16) float s_h1 [2][2][K][HH];  // 5 KB

    const int tid = threadIdx.x;
    const int w   = tid >> 5;
    const int i   = tid & 31;
    const bool act = (i < HH);
    const unsigned FULL = 0xFFFFFFFFu;

    const bool low = (w < 4);
    const int bs   = low ? (w >> 1) : ((w - 4) >> 1);
    const int sub  = low ? (w & 1) : (w & 1);   // 0: rz / L0,  1: n / L1
    const int b    = blockIdx.x * 2 + bs;

    // ---- prime: GX1n warps copy gx0 chunk 0 into s_gx0 slot 0 --------------
    if (low && sub == 1) {
        const float4* src = (const float4*)(g_gx0 + ((size_t)b * TT) * GG);
        float4* dst = (float4*)&s_gx0[bs][0][0][0];
        for (int idx = i; idx < (K * GG) / 4; idx += 32) dst[idx] = src[idx];
    }
    __syncthreads();

    if (low && sub == 0) {
        // ============ GX1rz: r,z rows of gx1 = W_ih1 . h0 (prescaled) ========
        u64 wi[20];
        float br = 0.f, bz = 0.f;
#pragma unroll
        for (int g = 0; g < 2; ++g)
#pragma unroll
            for (int k = 0; k < 10; ++k)
                wi[g * 10 + k] = act ? pack2(0.5f * W_ih1[(g * HH + i) * HH + 2 * k],
                                             0.5f * W_ih1[(g * HH + i) * HH + 2 * k + 1])
                                     : pack2(0.f, 0.f);
        if (act) { br = 0.5f * b_ih1[i]; bz = 0.5f * b_ih1[HH + i]; }

        for (int c = 0; c < NC + 3; ++c) {
            const int cn = c - 1;
            if (cn >= 0 && cn < NC) {
                const float* hr = &s_h0[bs][cn & 1][0][0];
                float* go = &s_gx1[bs][cn & 1][0][0];
#pragma unroll 4
                for (int s = 0; s < K; ++s) {
                    const u64* hv = (const u64*)(hr + s * HH);
                    u64 qr = pack2(br, 0.f), qz = pack2(bz, 0.f);
#pragma unroll
                    for (int k = 0; k < 10; ++k) {
                        u64 h2 = hv[k];
                        fma2(qr, wi[k],      h2);
                        fma2(qz, wi[10 + k], h2);
                    }
                    if (act) {
                        go[s * GG + i]      = hsum2(qr);
                        go[s * GG + HH + i] = hsum2(qz);
                    }
                }
            }
            __syncthreads();
        }
    } else if (low) {
        // ===== GX1n + gx0-DMA + output head ==================================
        u64 wi[10];           // W_ih1 n-rows (unscaled)
        u64 wo2[10];          // W_o pairs (same in all lanes)
        float bn = 0.f;
#pragma unroll
        for (int k = 0; k < 10; ++k) {
            wi[k] = act ? pack2(W_ih1[(2 * HH + i) * HH + 2 * k],
                                W_ih1[(2 * HH + i) * HH + 2 * k + 1])
                        : pack2(0.f, 0.f);
            wo2[k] = pack2(W_o[2 * k], W_o[2 * k + 1]);
        }
        if (act) bn = b_ih1[2 * HH + i];
        const float bo = b_o[0];
        const float* gsrc = g_gx0 + (size_t)b * TT * GG;
        float* ob = out + (size_t)b * TT;

        for (int c = 0; c < NC + 3; ++c) {
            // DMA fetch gx0 chunk c+1 (LDG latency hidden by whole iteration)
            float4 pf[2];
            const bool dm = (c + 1 < NC);
            if (dm) {
                const float4* src = (const float4*)(gsrc + (size_t)(c + 1) * K * GG);
                pf[0] = src[i];
                pf[1] = src[i + 32];
                // remaining (240-64)/32 per-lane elements loaded below
            }
            float4 pf2[6];
            if (dm) {
                const float4* src = (const float4*)(gsrc + (size_t)(c + 1) * K * GG);
#pragma unroll
                for (int j = 0; j < 6; ++j) {
                    int idx = i + 64 + 32 * j;
                    if (idx < (K * GG) / 4) pf2[j] = src[idx];
                }
            }

            // n-gate of gx1 for chunk c-1
            const int cn = c - 1;
            if (cn >= 0 && cn < NC) {
                const float* hr = &s_h0[bs][cn & 1][0][0];
                float* go = &s_gx1[bs][cn & 1][0][0];
#pragma unroll 4
                for (int s = 0; s < K; ++s) {
                    const u64* hv = (const u64*)(hr + s * HH);
                    u64 qn = pack2(bn, 0.f);
#pragma unroll
                    for (int k = 0; k < 10; ++k)
                        fma2(qn, wi[k], hv[k]);
                    if (act) go[s * GG + 2 * HH + i] = hsum2(qn);
                }
            }

            // output head for chunk c-3: lane l<K computes step l's dot
            const int ch = c - 3;
            if (ch >= 0 && ch < NC && i < K) {
                const u64* hv = (const u64*)&s_h1[bs][ch & 1][i][0];
                u64 acc = pack2(bo, 0.f);
#pragma unroll
                for (int k = 0; k < 10; ++k)
                    fma2(acc, wo2[k], hv[k]);
                ob[ch * K + i] = hsum2(acc);
            }

            // deposit DMA chunk
            if (dm) {
                float4* dst = (float4*)&s_gx0[bs][(c + 1) & 1][0][0];
                dst[i]      = pf[0];
                dst[i + 32] = pf[1];
#pragma unroll
                for (int j = 0; j < 6; ++j) {
                    int idx = i + 64 + 32 * j;
                    if (idx < (K * GG) / 4) dst[idx] = pf2[j];
                }
            }
            __syncthreads();
        }
    } else {
        // ============ L0 / L1: pure recurrence chains ========================
        const bool isL0  = (sub == 0);
        const float* Whh = isL0 ? W_hh0 : W_hh1;
        const float* bhh = isL0 ? b_hh0 : b_hh1;
        const int lag    = isL0 ? 0 : 2;
        const int layer  = isL0 ? 0 : 1;

        u64 wh[30];
        float br = 0.f, bz = 0.f, bn = 0.f, h = 0.f;
#pragma unroll
        for (int g = 0; g < 3; ++g) {
            const float sc = (g < 2) ? 0.5f : 1.0f;
#pragma unroll
            for (int k = 0; k < 10; ++k)
                wh[g * 10 + k] = act ? pack2(sc * Whh[(g * HH + i) * HH + 2 * k],
                                             sc * Whh[(g * HH + i) * HH + 2 * k + 1])
                                     : pack2(0.f, 0.f);
        }
        if (act) {
            br = 0.5f * bhh[i]; bz = 0.5f * bhh[HH + i]; bn = bhh[2 * HH + i];
            h = h0in[(b * 2 + layer) * HH + i];
        }

        // initial broadcast of h (once; shfl is fine here)
        u64 hp[10];
#pragma unroll
        for (int k = 0; k < 10; ++k)
            hp[k] = pack2(__shfl_sync(FULL, h, 2 * k),
                          __shfl_sync(FULL, h, 2 * k + 1));

        for (int c = 0; c < NC + 3; ++c) {
            const int cc = c - lag;
            if (cc >= 0 && cc < NC) {
                const float* gx = isL0 ? &s_gx0[bs][cc & 1][0][0]
                                       : &s_gx1[bs][cc & 1][0][0];
                float* hw = isL0 ? &s_h0[bs][cc & 1][0][0]
                                 : &s_h1[bs][cc & 1][0][0];
#pragma unroll 2
                for (int s = 0; s < K; ++s) {
                    float gr = 0.f, gz = 0.f, gn = 0.f;
                    if (act) {
                        gr = gx[s * GG + i];
                        gz = gx[s * GG + HH + i];
                        gn = gx[s * GG + 2 * HH + i];
                    }
                    // gate dots, grouped so r completes earliest
                    u64 ar = pack2(br, 0.f);
#pragma unroll
                    for (int k = 0; k < 10; ++k) fma2(ar, wh[k], hp[k]);
                    u64 az = pack2(bz, 0.f);
#pragma unroll
                    for (int k = 0; k < 10; ++k) fma2(az, wh[10 + k], hp[k]);
                    u64 an = pack2(bn, 0.f);
#pragma unroll
                    for (int k = 0; k < 10; ++k) fma2(an, wh[20 + k], hp[k]);

                    const float r = fmaf(tanha(gr + hsum2(ar)), 0.5f, 0.5f);
                    const float z = fmaf(tanha(gz + hsum2(az)), 0.5f, 0.5f);
                    const float n = tanha(fmaf(r, hsum2(an), gn));
                    h = fmaf(z, h - n, n);

                    // exchange through the s_h row (also feeds GX1/head warps)
                    if (act) hw[s * HH + i] = h;
                    __syncwarp();
                    const u64* hv = (const u64*)(hw + s * HH);
#pragma unroll
                    for (int k = 0; k < 10; ++k) hp[k] = hv[k];
                }
            }
            __syncthreads();
        }
        if (act) out[(size_t)BB * TT + (b * 2 + layer) * HH + i] = h;
    }
}

// ---------------------------------------------------------------------------
extern "C" void kernel_launch(void* const* d_in, const int* in_sizes, int n_in,
                              void* d_out, int out_size) {
    const float* x     = (const float*)d_in[0];
    const float* h0    = (const float*)d_in[1];
    const float* W_ih0 = (const float*)d_in[2];
    const float* W_hh0 = (const float*)d_in[3];
    const float* b_ih0 = (const float*)d_in[4];
    const float* b_hh0 = (const float*)d_in[5];
    const float* W_ih1 = (const float*)d_in[6];
    const float* W_hh1 = (const float*)d_in[7];
    const float* b_ih1 = (const float*)d_in[8];
    const float* b_hh1 = (const float*)d_in[9];
    const float* W_o   = (const float*)d_in[10];
    const float* b_o   = (const float*)d_in[11];

    // Phase 1: bulk gx0 GEMM (prescaled r/z rows)
    gx0_kernel<<<(BB * TT) / 4, dim3(64, 4)>>>(x, W_ih0, b_ih0);
    // Phase 2: fused recurrent pipeline
    gru_main_kernel<<<BB / 2, 256>>>(h0, W_hh0, b_hh0, W_ih1, b_ih1,
                                     W_hh1, b_hh1, W_o, b_o, (float*)d_out);
}

// round 9
// speedup vs baseline: 4.3454x; 4.3454x over previous
#include <cuda_runtime.h>

// Fixed problem shape
#define BB 256
#define TT 4096
#define CC 16
#define HH 20
#define GG 60
#define K  16
#define NC (TT / K)   // 256 chunks

typedef unsigned long long u64;

__device__ __forceinline__ u64 pack2(float a, float b) {
    u64 r; asm("mov.b64 %0,{%1,%2};" : "=l"(r) : "f"(a), "f"(b)); return r;
}
__device__ __forceinline__ void fma2(u64& d, u64 a, u64 b) {
    asm("fma.rn.f32x2 %0,%1,%2,%0;" : "+l"(d) : "l"(a), "l"(b));
}
__device__ __forceinline__ float hsum2(u64 v) {
    float x, y; asm("mov.b64 {%0,%1},%2;" : "=f"(x), "=f"(y) : "l"(v)); return x + y;
}
__device__ __forceinline__ float tanha(float x) {
    float y; asm("tanh.approx.f32 %0,%1;" : "=f"(y) : "f"(x)); return y;
}

// ---------------------------------------------------------------------------
// Single fused kernel. 2 batches per block, 8 warps, 128 blocks (1/SM).
// Warp map (SMSP = w%4; latency-critical chain warps at HIGH wid):
//   w0=GX0+xDMA(A) S0   w1=GX1+head(A) S1   w2=GX0+xDMA(B) S2   w3=GX1+head(B) S3
//   w4=L0(A)       S0   w5=L1(A)       S1   w6=L0(B)       S2   w7=L1(B)      S3
// Iteration c (one __syncthreads, all rings 2-deep, opposite parities):
//   GX0:  x chunk c (s_x) -> s_gx0 chunk c          (24 fma2/step, prescaled)
//         + prefetch x chunk c+1 global -> s_x
//   L0:   s_gx0 chunk c-1 -> s_h0 chunk c-1          (pure 30-fma2 chain)
//   GX1:  s_h0 chunk c-2 -> s_gx1 chunk c-2          (30 fma2/step)
//   L1:   s_gx1 chunk c-3 -> s_h1 chunk c-3          (pure chain)
//   head: s_h1 chunk c-4 -> out  (16 head dots parallel across lanes, on GX1 warp)
// Chains exchange h through their s_h ring rows (STS + syncwarp + LDS.64);
// the same rows feed the GX1/head consumer warps.
// r/z weights, biases and gx rows pre-scaled by 0.5:
//   sigmoid(s) = fma(tanh.approx(prescaled_sum), 0.5, 0.5).
// ---------------------------------------------------------------------------
__global__ void __launch_bounds__(256, 1)
fused_gru_kernel(const float* __restrict__ x,      // [B,T,C]
                 const float* __restrict__ h0in,   // [B,2,H]
                 const float* __restrict__ W_ih0, const float* __restrict__ W_hh0,
                 const float* __restrict__ b_ih0, const float* __restrict__ b_hh0,
                 const float* __restrict__ W_ih1, const float* __restrict__ W_hh1,
                 const float* __restrict__ b_ih1, const float* __restrict__ b_hh1,
                 const float* __restrict__ W_o,   const float* __restrict__ b_o,
                 float* __restrict__ out)          // o[B*T] then h_n[B,2,H]
{
    __shared__ __align__(16) float s_x  [2][2][K][CC];  // 4 KB
    __shared__ __align__(16) float s_gx0[2][2][K][GG];  // 15 KB
    __shared__ __align__(16) float s_gx1[2][2][K][GG];  // 15 KB
    __shared__ __align__(16) float s_h0 [2][2][K][HH];  // 5 KB
    __shared__ __align__(16) float s_h1 [2][2][K][HH];  // 5 KB

    const int tid = threadIdx.x;
    const int w   = tid >> 5;
    const int i   = tid & 31;
    const bool act = (i < HH);
    const unsigned FULL = 0xFFFFFFFFu;

    const bool low  = (w < 4);
    const int bs    = low ? (w >> 1) : ((w - 4) >> 1);
    const int kind  = w & 1;               // low: 0=GX0 1=GX1+head ; high: 0=L0 1=L1
    const int b     = blockIdx.x * 2 + bs;
    const float* xb = x + (size_t)b * TT * CC;

    // ---- prime x chunk 0 (GX0 warps): K*CC = 256 floats = 64 float4 --------
    if (low && kind == 0) {
        const float4* src = (const float4*)xb;
        float4* dst = (float4*)&s_x[bs][0][0][0];
        dst[i] = src[i]; dst[i + 32] = src[i + 32];
    }
    __syncthreads();

    if (low && kind == 0) {
        // ============ GX0 + x DMA: gx0 = W_ih0 . x_t + b_ih0 (rz prescaled) ==
        u64 wp[24];
        float br = 0.f, bz = 0.f, bn = 0.f;
#pragma unroll
        for (int g = 0; g < 3; ++g) {
            const float sc = (g < 2) ? 0.5f : 1.0f;
#pragma unroll
            for (int k = 0; k < 8; ++k)
                wp[g * 8 + k] = act ? pack2(sc * W_ih0[(g * HH + i) * CC + 2 * k],
                                            sc * W_ih0[(g * HH + i) * CC + 2 * k + 1])
                                    : pack2(0.f, 0.f);
        }
        if (act) { br = 0.5f * b_ih0[i]; bz = 0.5f * b_ih0[HH + i]; bn = b_ih0[2 * HH + i]; }

        for (int c = 0; c < NC + 4; ++c) {
            float4 pf0, pf1;
            const bool pf = (c + 1 < NC);
            if (pf) {
                const float4* src = (const float4*)(xb + (size_t)(c + 1) * K * CC);
                pf0 = src[i]; pf1 = src[i + 32];
            }
            if (c < NC) {
                const float* xs = &s_x[bs][c & 1][0][0];
                float* go = &s_gx0[bs][c & 1][0][0];
#pragma unroll 4
                for (int s = 0; s < K; ++s) {
                    u64 ar = pack2(br, 0.f), az = pack2(bz, 0.f), an = pack2(bn, 0.f);
                    const float* xr = xs + s * CC;
#pragma unroll
                    for (int k = 0; k < 8; ++k) {
                        u64 xv = *(const u64*)(xr + 2 * k);   // LDS.64 broadcast
                        fma2(ar, wp[k],      xv);
                        fma2(az, wp[8 + k],  xv);
                        fma2(an, wp[16 + k], xv);
                    }
                    if (act) {
                        go[s * GG + i]          = hsum2(ar);
                        go[s * GG + HH + i]     = hsum2(az);
                        go[s * GG + 2 * HH + i] = hsum2(an);
                    }
                }
            }
            if (pf) {
                float4* dst = (float4*)&s_x[bs][(c + 1) & 1][0][0];
                dst[i] = pf0; dst[i + 32] = pf1;
            }
            __syncthreads();
        }
    } else if (low) {
        // ============ GX1 + output head ======================================
        u64 wi[30];           // W_ih1 rows; rz prescaled
        u64 wo2[10];          // W_o pairs (same in all lanes)
        float br = 0.f, bz = 0.f, bn = 0.f;
#pragma unroll
        for (int g = 0; g < 3; ++g) {
            const float sc = (g < 2) ? 0.5f : 1.0f;
#pragma unroll
            for (int k = 0; k < 10; ++k)
                wi[g * 10 + k] = act ? pack2(sc * W_ih1[(g * HH + i) * HH + 2 * k],
                                             sc * W_ih1[(g * HH + i) * HH + 2 * k + 1])
                                     : pack2(0.f, 0.f);
        }
#pragma unroll
        for (int k = 0; k < 10; ++k)
            wo2[k] = pack2(W_o[2 * k], W_o[2 * k + 1]);
        if (act) { br = 0.5f * b_ih1[i]; bz = 0.5f * b_ih1[HH + i]; bn = b_ih1[2 * HH + i]; }
        const float bo = b_o[0];
        float* ob = out + (size_t)b * TT;

        for (int c = 0; c < NC + 4; ++c) {
            const int cg = c - 2;
            if (cg >= 0 && cg < NC) {
                const float* hr = &s_h0[bs][cg & 1][0][0];
                float* go = &s_gx1[bs][cg & 1][0][0];
#pragma unroll 4
                for (int s = 0; s < K; ++s) {
                    const u64* hv = (const u64*)(hr + s * HH);
                    u64 qr = pack2(br, 0.f), qz = pack2(bz, 0.f), qn = pack2(bn, 0.f);
#pragma unroll
                    for (int k = 0; k < 10; ++k) {
                        u64 h2 = hv[k];
                        fma2(qr, wi[k],      h2);
                        fma2(qz, wi[10 + k], h2);
                        fma2(qn, wi[20 + k], h2);
                    }
                    if (act) {
                        go[s * GG + i]          = hsum2(qr);
                        go[s * GG + HH + i]     = hsum2(qz);
                        go[s * GG + 2 * HH + i] = hsum2(qn);
                    }
                }
            }
            // output head for chunk c-4: lane l<K computes step l's dot
            const int ch = c - 4;
            if (ch >= 0 && i < K) {
                const u64* hv = (const u64*)&s_h1[bs][ch & 1][i][0];
                u64 acc = pack2(bo, 0.f);
#pragma unroll
                for (int k = 0; k < 10; ++k)
                    fma2(acc, wo2[k], hv[k]);
                ob[ch * K + i] = hsum2(acc);
            }
            __syncthreads();
        }
    } else {
        // ============ L0 / L1: pure recurrence chains ========================
        const bool isL0  = (kind == 0);
        const float* Whh = isL0 ? W_hh0 : W_hh1;
        const float* bhh = isL0 ? b_hh0 : b_hh1;
        const int lag    = isL0 ? 1 : 3;
        const int layer  = isL0 ? 0 : 1;

        u64 wh[30];
        float br = 0.f, bz = 0.f, bn = 0.f, h = 0.f;
#pragma unroll
        for (int g = 0; g < 3; ++g) {
            const float sc = (g < 2) ? 0.5f : 1.0f;
#pragma unroll
            for (int k = 0; k < 10; ++k)
                wh[g * 10 + k] = act ? pack2(sc * Whh[(g * HH + i) * HH + 2 * k],
                                             sc * Whh[(g * HH + i) * HH + 2 * k + 1])
                                     : pack2(0.f, 0.f);
        }
        if (act) {
            br = 0.5f * bhh[i]; bz = 0.5f * bhh[HH + i]; bn = bhh[2 * HH + i];
            h = h0in[(b * 2 + layer) * HH + i];
        }

        // initial broadcast of h (once)
        u64 hp[10];
#pragma unroll
        for (int k = 0; k < 10; ++k)
            hp[k] = pack2(__shfl_sync(FULL, h, 2 * k),
                          __shfl_sync(FULL, h, 2 * k + 1));

        for (int c = 0; c < NC + 4; ++c) {
            const int cc = c - lag;
            if (cc >= 0 && cc < NC) {
                const float* gx = isL0 ? &s_gx0[bs][cc & 1][0][0]
                                       : &s_gx1[bs][cc & 1][0][0];
                float* hw = isL0 ? &s_h0[bs][cc & 1][0][0]
                                 : &s_h1[bs][cc & 1][0][0];
#pragma unroll 2
                for (int s = 0; s < K; ++s) {
                    float gr = 0.f, gz = 0.f, gn = 0.f;
                    if (act) {
                        gr = gx[s * GG + i];
                        gz = gx[s * GG + HH + i];
                        gn = gx[s * GG + 2 * HH + i];
                    }
                    // gate dots, grouped so r completes earliest
                    u64 ar = pack2(br, 0.f);
#pragma unroll
                    for (int k = 0; k < 10; ++k) fma2(ar, wh[k], hp[k]);
                    u64 az = pack2(bz, 0.f);
#pragma unroll
                    for (int k = 0; k < 10; ++k) fma2(az, wh[10 + k], hp[k]);
                    u64 an = pack2(bn, 0.f);
#pragma unroll
                    for (int k = 0; k < 10; ++k) fma2(an, wh[20 + k], hp[k]);

                    const float r = fmaf(tanha(gr + hsum2(ar)), 0.5f, 0.5f);
                    const float z = fmaf(tanha(gz + hsum2(az)), 0.5f, 0.5f);
                    const float n = tanha(fmaf(r, hsum2(an), gn));
                    h = fmaf(z, h - n, n);

                    // exchange through the s_h row (also feeds GX1/head warps)
                    if (act) hw[s * HH + i] = h;
                    __syncwarp();
                    const u64* hv = (const u64*)(hw + s * HH);
#pragma unroll
                    for (int k = 0; k < 10; ++k) hp[k] = hv[k];
                }
            }
            __syncthreads();
        }
        if (act) out[(size_t)BB * TT + (b * 2 + layer) * HH + i] = h;
    }
}

// ---------------------------------------------------------------------------
extern "C" void kernel_launch(void* const* d_in, const int* in_sizes, int n_in,
                              void* d_out, int out_size) {
    const float* x     = (const float*)d_in[0];
    const float* h0    = (const float*)d_in[1];
    const float* W_ih0 = (const float*)d_in[2];
    const float* W_hh0 = (const float*)d_in[3];
    const float* b_ih0 = (const float*)d_in[4];
    const float* b_hh0 = (const float*)d_in[5];
    const float* W_ih1 = (const float*)d_in[6];
    const float* W_hh1 = (const float*)d_in[7];
    const float* b_ih1 = (const float*)d_in[8];
    const float* b_hh1 = (const float*)d_in[9];
    const float* W_o   = (const float*)d_in[10];
    const float* b_o   = (const float*)d_in[11];

    fused_gru_kernel<<<BB / 2, 256>>>(x, h0, W_ih0, W_hh0, b_ih0, b_hh0,
                                      W_ih1, W_hh1, b_ih1, b_hh1, W_o, b_o,
                                      (float*)d_out);
}